// round 9
// baseline (speedup 1.0000x reference)
#include <cuda_runtime.h>
#include <cuda_bf16.h>
#include <math.h>

// ----------------------------------------------------------------------------
// Attention_13314398617962   (t=512, b=64, s=1024, hu=1024)
//   scores[t,b] = MLP(concat(si[b], h[t,b]))   (2048 -> 10 -> 5 -> 1, BN+relu)
//   a = softmax(scores.flatten())              (over all 32768)
//   ci[b,:] = sum_tau a[tau] * h[tau_t, tau_b, :]   (tau < 512)
// ----------------------------------------------------------------------------

#define T_DIM 512
#define B_DIM 64
#define HU 1024
#define NROWS (T_DIM * B_DIM)   // 32768
#define RPB 16                  // rows per block in score kernel
#define NBLK (NROWS / RPB)      // 2048
#define RSTRIDE 324             // floats per row-slot: 2 jhalves x 32 parts x 5 + pad

__device__ float g_pre0[B_DIM * 10];   // si @ W0[:1024] per b (raw dot)
__device__ float g_ep[30];             // s0[10] t0[10] s1[5] t1[5]
__device__ float g_scores[T_DIM];      // raw scores for rows < 512
__device__ float g_w[T_DIM];           // softmax weights
__device__ float g_bmax[NBLK];
__device__ float g_bsum[NBLK];

// ---------------------------------------------------------------------------
__device__ __forceinline__ void ffma2(unsigned long long& d,
                                      unsigned long long a,
                                      unsigned long long b)
{
    asm("fma.rn.f32x2 %0, %1, %2, %0;" : "+l"(d) : "l"(a), "l"(b));
}
__device__ __forceinline__ void fmul2(unsigned long long& d,
                                      unsigned long long a,
                                      unsigned long long b)
{
    asm("mul.rn.f32x2 %0, %1, %2;" : "=l"(d) : "l"(a), "l"(b));
}
__device__ __forceinline__ unsigned long long pack2(float x)
{
    unsigned long long r;
    asm("mov.b64 %0, {%1, %1};" : "=l"(r) : "f"(x));
    return r;
}
__device__ __forceinline__ unsigned long long packpair(float a, float b)
{
    unsigned long long r;
    asm("mov.b64 %0, {%1, %2};" : "=l"(r) : "f"(a), "f"(b));
    return r;
}
__device__ __forceinline__ void unpack2(unsigned long long v, float& lo, float& hi)
{
    asm("mov.b64 {%0, %1}, %2;" : "=f"(lo), "=f"(hi) : "l"(v));
}

// ---------------------------------------------------------------------------
// K0: per-b si contribution (coalesced W0 reads) + folded BN constants.
// ---------------------------------------------------------------------------
__global__ __launch_bounds__(256)
void prep_kernel(const float* __restrict__ si,
                 const float* __restrict__ W0,
                 const float* __restrict__ b0,
                 const float* __restrict__ g0,
                 const float* __restrict__ be0,
                 const float* __restrict__ m0,
                 const float* __restrict__ v0,
                 const float* __restrict__ b1,
                 const float* __restrict__ g1,
                 const float* __restrict__ be1,
                 const float* __restrict__ m1,
                 const float* __restrict__ v1)
{
    __shared__ float red[64][10];

    int b = blockIdx.x;
    int tid = threadIdx.x;
    int lane = tid & 31;
    int warp = tid >> 5;

    float wv[40];
    {
        const float4* wp = reinterpret_cast<const float4*>(W0 + 4 * tid * 10);
#pragma unroll
        for (int i = 0; i < 10; ++i)
            reinterpret_cast<float4*>(wv)[i] = wp[i];
    }
    float4 sv = reinterpret_cast<const float4*>(si + b * 1024)[tid];

    float pj[10];
#pragma unroll
    for (int j = 0; j < 10; ++j) {
        float a = sv.x * wv[j];
        a = fmaf(sv.y, wv[10 + j], a);
        a = fmaf(sv.z, wv[20 + j], a);
        a = fmaf(sv.w, wv[30 + j], a);
        pj[j] = a;
    }
#pragma unroll
    for (int j = 0; j < 10; ++j) {
        pj[j] += __shfl_xor_sync(0xffffffffu, pj[j], 16);
        pj[j] += __shfl_xor_sync(0xffffffffu, pj[j], 8);
    }
    if (lane < 8) {
#pragma unroll
        for (int j = 0; j < 10; ++j) red[warp * 8 + lane][j] = pj[j];
    }
    __syncthreads();

    if (tid < 10) {
        float s = 0.f;
#pragma unroll
        for (int q = 0; q < 64; ++q) s += red[q][tid];
        g_pre0[b * 10 + tid] = s;
    }

    if (b == 0) {
        if (tid >= 32 && tid < 42) {
            int i = tid - 32;
            float s = g0[i] * (1.0f / sqrtf(v0[i] + 1e-5f));
            g_ep[i] = s;
            g_ep[10 + i] = (b0[i] - m0[i]) * s + be0[i];
        } else if (tid >= 64 && tid < 69) {
            int i = tid - 64;
            float s = g1[i] * (1.0f / sqrtf(v1[i] + 1e-5f));
            g_ep[20 + i] = s;
            g_ep[25 + i] = (b1[i] - m1[i]) * s + be1[i];
        }
    }
}

// ---------------------------------------------------------------------------
// K1: scores + per-block online softmax stats. 16 rows/block, 2048 blocks.
// j-SPLIT (fixed): 256 threads = 2 groups of 128; group jg computes outputs
// j = jg*5..jg*5+4 over the FULL row: thread ts owns k = 4*ts..4*ts+3 AND
// 512+4*ts..512+4*ts+3 (8 k) -> 40 weight floats = 24 packed f32x2 regs.
// Both groups load the same 2 float4 per row (group 1 hits L1).
// 5-deep pair prefetch ring (~113 regs, no spills at 2 CTAs/SM; distance
// 5 iters > DRAM latency; 80 KB/SM in flight).
// Per warp-row: 2 LDG.128, 24 FFMA2, 10 SHFL, 5 STS.32 (lane<8)
// -> block MIO 120/row (vs 200 in R4).
// ---------------------------------------------------------------------------
__global__ __launch_bounds__(256, 2)
void score_kernel(const float* __restrict__ h,
                  const float* __restrict__ W0,
                  const float* __restrict__ W1,
                  const float* __restrict__ W2,
                  const float* __restrict__ b2)
{
    __shared__ float red[RPB * RSTRIDE];      // [row][jg*160 + part*5 + jj]  20.7 KB
    __shared__ float pre0s[RPB * 10];
    __shared__ float dsum[RPB * 10];
    __shared__ float epi[86];                 // s0 t0 s1 t1 W1[50] W2[5] b2

    int tid  = threadIdx.x;
    int lane = tid & 31;
    int jg   = tid >> 7;                      // j-group 0/1
    int ts   = tid & 127;                     // thread within group
    int wg   = (tid >> 5) & 3;                // warp within group
    int rowbase = blockIdx.x * RPB;
    int bbase   = rowbase & 63;

    if (tid < 30)                  epi[tid] = g_ep[tid];
    if (tid >= 32 && tid < 82)     epi[30 + tid - 32] = W1[tid - 32];
    if (tid >= 96 && tid < 101)    epi[80 + tid - 96] = W2[tid - 96];
    if (tid == 101)                epi[85] = b2[0];
    if (tid < RPB * 10)            pre0s[tid] = g_pre0[bbase * 10 + tid];

    // 40 weight floats (8 k x 5 j) -> 24 packed f32x2: u[kk*3+p], pad 0
    unsigned long long u[24];
    {
        const float* wb0 = W0 + (1024 + 4 * ts) * 10 + jg * 5;        // k lo half
        const float* wb1 = W0 + (1024 + 512 + 4 * ts) * 10 + jg * 5;  // k hi half
#pragma unroll
        for (int kk = 0; kk < 4; ++kk) {
            u[kk * 3 + 0] = packpair(wb0[kk * 10 + 0], wb0[kk * 10 + 1]);
            u[kk * 3 + 1] = packpair(wb0[kk * 10 + 2], wb0[kk * 10 + 3]);
            u[kk * 3 + 2] = packpair(wb0[kk * 10 + 4], 0.f);
            u[12 + kk * 3 + 0] = packpair(wb1[kk * 10 + 0], wb1[kk * 10 + 1]);
            u[12 + kk * 3 + 1] = packpair(wb1[kk * 10 + 2], wb1[kk * 10 + 3]);
            u[12 + kk * 3 + 2] = packpair(wb1[kk * 10 + 4], 0.f);
        }
    }

    const float* hb = h + (size_t)rowbase * 1024 + 4 * ts;
    float4 PA[5], PB[5];
#pragma unroll
    for (int i = 0; i < 5; ++i) {
        PA[i] = *reinterpret_cast<const float4*>(hb + (size_t)i * 1024);
        PB[i] = *reinterpret_cast<const float4*>(hb + (size_t)i * 1024 + 512);
    }

    __syncthreads();   // smem staging visible

#pragma unroll
    for (int it = 0; it < RPB; ++it) {
        float4 ca = PA[it % 5];
        float4 cb = PB[it % 5];
        if (it < RPB - 5) {
            const float* pn = hb + (size_t)(it + 5) * 1024;
            PA[it % 5] = *reinterpret_cast<const float4*>(pn);
            PB[it % 5] = *reinterpret_cast<const float4*>(pn + 512);
        }

        unsigned long long acc[3];
        unsigned long long hh;
        hh = pack2(ca.x);
#pragma unroll
        for (int p = 0; p < 3; ++p) fmul2(acc[p], hh, u[p]);
        hh = pack2(ca.y);
#pragma unroll
        for (int p = 0; p < 3; ++p) ffma2(acc[p], hh, u[3 + p]);
        hh = pack2(ca.z);
#pragma unroll
        for (int p = 0; p < 3; ++p) ffma2(acc[p], hh, u[6 + p]);
        hh = pack2(ca.w);
#pragma unroll
        for (int p = 0; p < 3; ++p) ffma2(acc[p], hh, u[9 + p]);
        hh = pack2(cb.x);
#pragma unroll
        for (int p = 0; p < 3; ++p) ffma2(acc[p], hh, u[12 + p]);
        hh = pack2(cb.y);
#pragma unroll
        for (int p = 0; p < 3; ++p) ffma2(acc[p], hh, u[15 + p]);
        hh = pack2(cb.z);
#pragma unroll
        for (int p = 0; p < 3; ++p) ffma2(acc[p], hh, u[18 + p]);
        hh = pack2(cb.w);
#pragma unroll
        for (int p = 0; p < 3; ++p) ffma2(acc[p], hh, u[21 + p]);

        float pj[6];
#pragma unroll
        for (int p = 0; p < 3; ++p) unpack2(acc[p], pj[2 * p], pj[2 * p + 1]);

#pragma unroll
        for (int j = 0; j < 5; ++j) {
            pj[j] += __shfl_xor_sync(0xffffffffu, pj[j], 16);
            pj[j] += __shfl_xor_sync(0xffffffffu, pj[j], 8);
        }
        if (lane < 8) {
            float* rb = red + it * RSTRIDE + jg * 160 + (wg * 8 + lane) * 5;
#pragma unroll
            for (int j = 0; j < 5; ++j) rb[j] = pj[j];
        }
    }
    __syncthreads();

    // block reduce: 160 (row,j) sums, each over 32 partials (stride 5 floats)
    if (tid < RPB * 10) {
        int rl = tid / 10;
        int j  = tid - rl * 10;
        int jgg = j / 5;
        int jj  = j - jgg * 5;
        const float* base = red + rl * RSTRIDE + jgg * 160 + jj;
        float s0 = 0.f, s1 = 0.f, s2 = 0.f, s3 = 0.f;
#pragma unroll
        for (int q = 0; q < 8; ++q) {
            s0 += base[(4 * q) * 5];
            s1 += base[(4 * q + 1) * 5];
            s2 += base[(4 * q + 2) * 5];
            s3 += base[(4 * q + 3) * 5];
        }
        dsum[tid] = (s0 + s1) + (s2 + s3);
    }
    __syncthreads();

    // fused MLP epilogue (16 rows) + warp-0 online softmax stats
    if (tid < 32) {
        float sc = -1e30f;
        if (tid < RPB) {
            int row = rowbase + tid;
            float x0[10];
#pragma unroll
            for (int j = 0; j < 10; ++j) {
                float d = dsum[tid * 10 + j] + pre0s[tid * 10 + j];
                x0[j] = fmaxf(fmaf(d, epi[j], epi[10 + j]), 0.f);
            }
            sc = epi[85];
#pragma unroll
            for (int i = 0; i < 5; ++i) {
                float z = 0.f;
#pragma unroll
                for (int j = 0; j < 10; ++j)
                    z = fmaf(x0[j], epi[30 + j * 5 + i], z);
                float x1 = fmaxf(fmaf(z, epi[20 + i], epi[25 + i]), 0.f);
                sc = fmaf(x1, epi[80 + i], sc);
            }
            if (row < T_DIM) g_scores[row] = sc;
        }
        float m = sc;
#pragma unroll
        for (int o = 16; o > 0; o >>= 1)
            m = fmaxf(m, __shfl_xor_sync(0xffffffffu, m, o));
        float e = (tid < RPB) ? expf(sc - m) : 0.f;
#pragma unroll
        for (int o = 16; o > 0; o >>= 1)
            e += __shfl_xor_sync(0xffffffffu, e, o);
        if (tid == 0) {
            g_bmax[blockIdx.x] = m;
            g_bsum[blockIdx.x] = e;
        }
    }
}

// ---------------------------------------------------------------------------
// K2: combine 2048 (max, expsum) pairs -> M, S; write 512 weights.
// ---------------------------------------------------------------------------
__global__ void combine_kernel()
{
    __shared__ float sm[512];
    __shared__ float MS[2];
    int tid = threadIdx.x;

    float lm = -1e30f;
    float bm[4];
#pragma unroll
    for (int i = 0; i < 4; ++i) {
        bm[i] = g_bmax[tid * 4 + i];
        lm = fmaxf(lm, bm[i]);
    }
    sm[tid] = lm;
    __syncthreads();
    for (int s = 256; s > 0; s >>= 1) {
        if (tid < s) sm[tid] = fmaxf(sm[tid], sm[tid + s]);
        __syncthreads();
    }
    if (tid == 0) MS[0] = sm[0];
    __syncthreads();
    float M = MS[0];

    float ls = 0.f;
#pragma unroll
    for (int i = 0; i < 4; ++i)
        ls += g_bsum[tid * 4 + i] * expf(bm[i] - M);
    sm[tid] = ls;
    __syncthreads();
    for (int s = 256; s > 0; s >>= 1) {
        if (tid < s) sm[tid] += sm[tid + s];
        __syncthreads();
    }
    if (tid == 0) MS[1] = 1.0f / sm[0];
    __syncthreads();

    g_w[tid] = expf(g_scores[tid] - M) * MS[1];
}

// ---------------------------------------------------------------------------
// K3: ci[b,:] = sum_tau w[tau] * h[tau,b,:]
// grid (8 chunks of 128 cols, 64 b) x 512 threads (16 warps, t == w mod 16).
// (R4 configuration: best measured, 24.35 us)
// ---------------------------------------------------------------------------
__global__ __launch_bounds__(512)
void wsum_kernel(const float* __restrict__ h, float* __restrict__ out)
{
    __shared__ float ws[T_DIM];
    __shared__ float part[16][128];

    int tid  = threadIdx.x;
    int w    = tid >> 5;
    int lane = tid & 31;
    int c = blockIdx.x;           // 128-col chunk
    int b = blockIdx.y;

    if (tid < 128)
        reinterpret_cast<float4*>(ws)[tid] = reinterpret_cast<const float4*>(g_w)[tid];
    __syncthreads();

    const float* hp = h + (size_t)b * 1024 + c * 128 + 4 * lane;
    float4 acc = make_float4(0.f, 0.f, 0.f, 0.f);
#pragma unroll 8
    for (int i = 0; i < T_DIM / 16; ++i) {
        int t = i * 16 + w;
        float4 hv = *reinterpret_cast<const float4*>(hp + (size_t)t * (B_DIM * HU));
        float wv = ws[t];
        acc.x = fmaf(wv, hv.x, acc.x);
        acc.y = fmaf(wv, hv.y, acc.y);
        acc.z = fmaf(wv, hv.z, acc.z);
        acc.w = fmaf(wv, hv.w, acc.w);
    }
    *reinterpret_cast<float4*>(&part[w][4 * lane]) = acc;
    __syncthreads();

    if (tid < 128) {
        float s0 = part[0][tid], s1 = part[1][tid];
        float s2 = part[2][tid], s3 = part[3][tid];
#pragma unroll
        for (int q = 4; q < 16; q += 4) {
            s0 += part[q][tid];
            s1 += part[q + 1][tid];
            s2 += part[q + 2][tid];
            s3 += part[q + 3][tid];
        }
        out[b * 1024 + c * 128 + tid] = (s0 + s1) + (s2 + s3);
    }
}

// ---------------------------------------------------------------------------
extern "C" void kernel_launch(void* const* d_in, const int* in_sizes, int n_in,
                              void* d_out, int out_size)
{
    const float* si  = (const float*)d_in[0];
    const float* h   = (const float*)d_in[1];
    const float* W0  = (const float*)d_in[2];
    const float* b0  = (const float*)d_in[3];
    const float* g0  = (const float*)d_in[4];
    const float* be0 = (const float*)d_in[5];
    const float* m0  = (const float*)d_in[6];
    const float* v0  = (const float*)d_in[7];
    const float* W1  = (const float*)d_in[8];
    const float* b1  = (const float*)d_in[9];
    const float* g1  = (const float*)d_in[10];
    const float* be1 = (const float*)d_in[11];
    const float* m1  = (const float*)d_in[12];
    const float* v1  = (const float*)d_in[13];
    const float* W2  = (const float*)d_in[14];
    const float* b2  = (const float*)d_in[15];
    float* out = (float*)d_out;

    prep_kernel<<<B_DIM, 256>>>(si, W0, b0, g0, be0, m0, v0, b1, g1, be1, m1, v1);
    score_kernel<<<NBLK, 256>>>(h, W0, W1, W2, b2);
    combine_kernel<<<1, 512>>>();
    wsum_kernel<<<dim3(8, B_DIM), 512>>>(h, out);
}

// round 11
// speedup vs baseline: 1.4818x; 1.4818x over previous
#include <cuda_runtime.h>
#include <cuda_bf16.h>
#include <math.h>
#include <stdint.h>

// ----------------------------------------------------------------------------
// Attention_13314398617962   (t=512, b=64, s=1024, hu=1024)
//   scores[t,b] = MLP(concat(si[b], h[t,b]))   (2048 -> 10 -> 5 -> 1, BN+relu)
//   a = softmax(scores.flatten())              (over all 32768)
//   ci[b,:] = sum_tau a[tau] * h[tau_t, tau_b, :]   (tau < 512)
// ----------------------------------------------------------------------------

#define T_DIM 512
#define B_DIM 64
#define HU 1024
#define NROWS (T_DIM * B_DIM)   // 32768
#define RPB 16                  // rows per block in score kernel
#define NBLK (NROWS / RPB)      // 2048
#define RSTRIDE 644             // padded floats per row-slot in red[] (64 parts x 10)

// dynamic smem layout (floats): ring[16*1024] | red[RPB*RSTRIDE]
#define RING_FLOATS (16 * 1024)
#define RED_FLOATS  (RPB * RSTRIDE)
#define DYN_BYTES   ((RING_FLOATS + RED_FLOATS) * 4)

__device__ float g_pre0[B_DIM * 10];   // si @ W0[:1024] per b (raw dot)
__device__ float g_ep[30];             // s0[10] t0[10] s1[5] t1[5]
__device__ float g_scores[T_DIM];      // raw scores for rows < 512
__device__ float g_w[T_DIM];           // softmax weights
__device__ float g_bmax[NBLK];
__device__ float g_bsum[NBLK];

// ---------------------------------------------------------------------------
__device__ __forceinline__ void ffma2(unsigned long long& d,
                                      unsigned long long a,
                                      unsigned long long b)
{
    asm("fma.rn.f32x2 %0, %1, %2, %0;" : "+l"(d) : "l"(a), "l"(b));
}
__device__ __forceinline__ void fmul2(unsigned long long& d,
                                      unsigned long long a,
                                      unsigned long long b)
{
    asm("mul.rn.f32x2 %0, %1, %2;" : "=l"(d) : "l"(a), "l"(b));
}
__device__ __forceinline__ unsigned long long pack2(float x)
{
    unsigned long long r;
    asm("mov.b64 %0, {%1, %1};" : "=l"(r) : "f"(x));
    return r;
}
__device__ __forceinline__ void unpack2(unsigned long long v, float& lo, float& hi)
{
    asm("mov.b64 {%0, %1}, %2;" : "=f"(lo), "=f"(hi) : "l"(v));
}
__device__ __forceinline__ unsigned int smem_u32(const void* p)
{
    unsigned int a;
    asm("{ .reg .u64 t; cvta.to.shared.u64 t, %1; cvt.u32.u64 %0, t; }"
        : "=r"(a) : "l"(p));
    return a;
}

// ---------------------------------------------------------------------------
// K0: per-b si contribution (coalesced W0 reads) + folded BN constants.
// ---------------------------------------------------------------------------
__global__ __launch_bounds__(256)
void prep_kernel(const float* __restrict__ si,
                 const float* __restrict__ W0,
                 const float* __restrict__ b0,
                 const float* __restrict__ g0,
                 const float* __restrict__ be0,
                 const float* __restrict__ m0,
                 const float* __restrict__ v0,
                 const float* __restrict__ b1,
                 const float* __restrict__ g1,
                 const float* __restrict__ be1,
                 const float* __restrict__ m1,
                 const float* __restrict__ v1)
{
    __shared__ float red[64][10];

    int b = blockIdx.x;
    int tid = threadIdx.x;
    int lane = tid & 31;
    int warp = tid >> 5;

    float wv[40];
    {
        const float4* wp = reinterpret_cast<const float4*>(W0 + 4 * tid * 10);
#pragma unroll
        for (int i = 0; i < 10; ++i)
            reinterpret_cast<float4*>(wv)[i] = wp[i];
    }
    float4 sv = reinterpret_cast<const float4*>(si + b * 1024)[tid];

    float pj[10];
#pragma unroll
    for (int j = 0; j < 10; ++j) {
        float a = sv.x * wv[j];
        a = fmaf(sv.y, wv[10 + j], a);
        a = fmaf(sv.z, wv[20 + j], a);
        a = fmaf(sv.w, wv[30 + j], a);
        pj[j] = a;
    }
#pragma unroll
    for (int j = 0; j < 10; ++j) {
        pj[j] += __shfl_xor_sync(0xffffffffu, pj[j], 16);
        pj[j] += __shfl_xor_sync(0xffffffffu, pj[j], 8);
    }
    if (lane < 8) {
#pragma unroll
        for (int j = 0; j < 10; ++j) red[warp * 8 + lane][j] = pj[j];
    }
    __syncthreads();

    if (tid < 10) {
        float s = 0.f;
#pragma unroll
        for (int q = 0; q < 64; ++q) s += red[q][tid];
        g_pre0[b * 10 + tid] = s;
    }

    if (b == 0) {
        if (tid >= 32 && tid < 42) {
            int i = tid - 32;
            float s = g0[i] * (1.0f / sqrtf(v0[i] + 1e-5f));
            g_ep[i] = s;
            g_ep[10 + i] = (b0[i] - m0[i]) * s + be0[i];
        } else if (tid >= 64 && tid < 69) {
            int i = tid - 64;
            float s = g1[i] * (1.0f / sqrtf(v1[i] + 1e-5f));
            g_ep[20 + i] = s;
            g_ep[25 + i] = (b1[i] - m1[i]) * s + be1[i];
        }
    }
}

// ---------------------------------------------------------------------------
// K1: scores + per-block online softmax stats. 16 rows/block, 2048 blocks.
// cp.async PIPELINE: 256 threads, each copies ITS OWN 16B of every row into
// a 16-stage smem ring (64 KB) up front (16 commit groups). In-flight
// 32 KB/SM at 2 CTAs -> DRAM latency fully covered with ZERO prefetch
// registers. Each thread later reads only its own slot -> no barriers,
// no stage reuse -> no races. Chunked waits: wait_group 12/8/4/0 before
// each 4-row chunk. Compute per row identical to R3 (proven): 20 FFMA2,
// 2 shfl rounds, lane<8 float2 stores. ~80 regs, no spills.
// ---------------------------------------------------------------------------
__global__ __launch_bounds__(256, 2)
void score_kernel(const float* __restrict__ h,
                  const float* __restrict__ W0,
                  const float* __restrict__ W1,
                  const float* __restrict__ W2,
                  const float* __restrict__ b2)
{
    extern __shared__ float dyn[];            // ring | red
    float* ring = dyn;
    float* red  = dyn + RING_FLOATS;

    __shared__ float pre0s[RPB * 10];
    __shared__ float dsum[RPB * 10];
    __shared__ float epi[86];                 // s0 t0 s1 t1 W1[50] W2[5] b2

    int tid  = threadIdx.x;
    int lane = tid & 31;
    int warp = tid >> 5;
    int rowbase = blockIdx.x * RPB;
    int bbase   = rowbase & 63;

    // kick off all 16 row copies FIRST (maximize overlap with staging below)
    const float* hb = h + (size_t)rowbase * 1024 + 4 * tid;
    unsigned int ring_dst = smem_u32(ring) + tid * 16;
#pragma unroll
    for (int s = 0; s < 16; ++s) {
        asm volatile(
            "cp.async.cg.shared.global [%0], [%1], 16;\n\t"
            "cp.async.commit_group;"
            :: "r"(ring_dst + s * 4096), "l"(hb + (size_t)s * 1024) : "memory");
    }

    if (tid < 30)                  epi[tid] = g_ep[tid];
    if (tid >= 32 && tid < 82)     epi[30 + tid - 32] = W1[tid - 32];
    if (tid >= 96 && tid < 101)    epi[80 + tid - 96] = W2[tid - 96];
    if (tid == 101)                epi[85] = b2[0];
    if (tid < RPB * 10)            pre0s[tid] = g_pre0[bbase * 10 + tid];

    // 40 weight floats as 20 packed f32x2: u[kk*5+p]
    union { float4 v[10]; unsigned long long u[20]; } wr;
    {
        const float4* wp = reinterpret_cast<const float4*>(W0 + (1024 + 4 * tid) * 10);
#pragma unroll
        for (int i = 0; i < 10; ++i) wr.v[i] = wp[i];
    }

    float* myring = ring + tid * 4;
    float* myred  = red + (warp * 8 + (lane & 7)) * 10;

    auto do_row = [&](int it) {
        float4 cv = *reinterpret_cast<const float4*>(myring + it * 1024);

        unsigned long long acc[5];
        unsigned long long hh;
        hh = pack2(cv.x);
#pragma unroll
        for (int p = 0; p < 5; ++p) fmul2(acc[p], hh, wr.u[p]);
        hh = pack2(cv.y);
#pragma unroll
        for (int p = 0; p < 5; ++p) ffma2(acc[p], hh, wr.u[5 + p]);
        hh = pack2(cv.z);
#pragma unroll
        for (int p = 0; p < 5; ++p) ffma2(acc[p], hh, wr.u[10 + p]);
        hh = pack2(cv.w);
#pragma unroll
        for (int p = 0; p < 5; ++p) ffma2(acc[p], hh, wr.u[15 + p]);

        float pj[10];
#pragma unroll
        for (int p = 0; p < 5; ++p) unpack2(acc[p], pj[2 * p], pj[2 * p + 1]);

#pragma unroll
        for (int j = 0; j < 10; ++j) {
            pj[j] += __shfl_xor_sync(0xffffffffu, pj[j], 16);
            pj[j] += __shfl_xor_sync(0xffffffffu, pj[j], 8);
        }
        if (lane < 8) {
            float2* rb = reinterpret_cast<float2*>(myred + it * RSTRIDE);
#pragma unroll
            for (int p = 0; p < 5; ++p) rb[p] = make_float2(pj[2 * p], pj[2 * p + 1]);
        }
    };

    asm volatile("cp.async.wait_group 12;" ::: "memory");
    do_row(0);  do_row(1);  do_row(2);  do_row(3);
    asm volatile("cp.async.wait_group 8;" ::: "memory");
    do_row(4);  do_row(5);  do_row(6);  do_row(7);
    asm volatile("cp.async.wait_group 4;" ::: "memory");
    do_row(8);  do_row(9);  do_row(10); do_row(11);
    asm volatile("cp.async.wait_group 0;" ::: "memory");
    do_row(12); do_row(13); do_row(14); do_row(15);

    __syncthreads();

    // block reduce: 160 (row,j) sums, each over 64 partials (stride 10 floats)
    if (tid < RPB * 10) {
        int rl = tid / 10;
        int j  = tid - rl * 10;
        const float* base = red + rl * RSTRIDE + j;
        float s0 = 0.f, s1 = 0.f, s2 = 0.f, s3 = 0.f;
#pragma unroll
        for (int q = 0; q < 16; ++q) {
            s0 += base[(4 * q) * 10];
            s1 += base[(4 * q + 1) * 10];
            s2 += base[(4 * q + 2) * 10];
            s3 += base[(4 * q + 3) * 10];
        }
        dsum[tid] = (s0 + s1) + (s2 + s3);
    }
    __syncthreads();

    // fused MLP epilogue (16 rows) + warp-0 online softmax stats
    if (tid < 32) {
        float sc = -1e30f;
        if (tid < RPB) {
            int row = rowbase + tid;
            float x0[10];
#pragma unroll
            for (int j = 0; j < 10; ++j) {
                float d = dsum[tid * 10 + j] + pre0s[tid * 10 + j];
                x0[j] = fmaxf(fmaf(d, epi[j], epi[10 + j]), 0.f);
            }
            sc = epi[85];
#pragma unroll
            for (int i = 0; i < 5; ++i) {
                float z = 0.f;
#pragma unroll
                for (int j = 0; j < 10; ++j)
                    z = fmaf(x0[j], epi[30 + j * 5 + i], z);
                float x1 = fmaxf(fmaf(z, epi[20 + i], epi[25 + i]), 0.f);
                sc = fmaf(x1, epi[80 + i], sc);
            }
            if (row < T_DIM) g_scores[row] = sc;
        }
        float m = sc;
#pragma unroll
        for (int o = 16; o > 0; o >>= 1)
            m = fmaxf(m, __shfl_xor_sync(0xffffffffu, m, o));
        float e = (tid < RPB) ? expf(sc - m) : 0.f;
#pragma unroll
        for (int o = 16; o > 0; o >>= 1)
            e += __shfl_xor_sync(0xffffffffu, e, o);
        if (tid == 0) {
            g_bmax[blockIdx.x] = m;
            g_bsum[blockIdx.x] = e;
        }
    }
}

// ---------------------------------------------------------------------------
// K2: combine 2048 (max, expsum) pairs -> M, S; write 512 weights.
// ---------------------------------------------------------------------------
__global__ void combine_kernel()
{
    __shared__ float sm[512];
    __shared__ float MS[2];
    int tid = threadIdx.x;

    float lm = -1e30f;
    float bm[4];
#pragma unroll
    for (int i = 0; i < 4; ++i) {
        bm[i] = g_bmax[tid * 4 + i];
        lm = fmaxf(lm, bm[i]);
    }
    sm[tid] = lm;
    __syncthreads();
    for (int s = 256; s > 0; s >>= 1) {
        if (tid < s) sm[tid] = fmaxf(sm[tid], sm[tid + s]);
        __syncthreads();
    }
    if (tid == 0) MS[0] = sm[0];
    __syncthreads();
    float M = MS[0];

    float ls = 0.f;
#pragma unroll
    for (int i = 0; i < 4; ++i)
        ls += g_bsum[tid * 4 + i] * expf(bm[i] - M);
    sm[tid] = ls;
    __syncthreads();
    for (int s = 256; s > 0; s >>= 1) {
        if (tid < s) sm[tid] += sm[tid + s];
        __syncthreads();
    }
    if (tid == 0) MS[1] = 1.0f / sm[0];
    __syncthreads();

    g_w[tid] = expf(g_scores[tid] - M) * MS[1];
}

// ---------------------------------------------------------------------------
// K3: ci[b,:] = sum_tau w[tau] * h[tau,b,:]
// grid (8 chunks of 128 cols, 64 b) x 512 threads (16 warps, t == w mod 16).
// (R4 configuration: best measured, 24.35 us)
// ---------------------------------------------------------------------------
__global__ __launch_bounds__(512)
void wsum_kernel(const float* __restrict__ h, float* __restrict__ out)
{
    __shared__ float ws[T_DIM];
    __shared__ float part[16][128];

    int tid  = threadIdx.x;
    int w    = tid >> 5;
    int lane = tid & 31;
    int c = blockIdx.x;           // 128-col chunk
    int b = blockIdx.y;

    if (tid < 128)
        reinterpret_cast<float4*>(ws)[tid] = reinterpret_cast<const float4*>(g_w)[tid];
    __syncthreads();

    const float* hp = h + (size_t)b * 1024 + c * 128 + 4 * lane;
    float4 acc = make_float4(0.f, 0.f, 0.f, 0.f);
#pragma unroll 8
    for (int i = 0; i < T_DIM / 16; ++i) {
        int t = i * 16 + w;
        float4 hv = *reinterpret_cast<const float4*>(hp + (size_t)t * (B_DIM * HU));
        float wv = ws[t];
        acc.x = fmaf(wv, hv.x, acc.x);
        acc.y = fmaf(wv, hv.y, acc.y);
        acc.z = fmaf(wv, hv.z, acc.z);
        acc.w = fmaf(wv, hv.w, acc.w);
    }
    *reinterpret_cast<float4*>(&part[w][4 * lane]) = acc;
    __syncthreads();

    if (tid < 128) {
        float s0 = part[0][tid], s1 = part[1][tid];
        float s2 = part[2][tid], s3 = part[3][tid];
#pragma unroll
        for (int q = 4; q < 16; q += 4) {
            s0 += part[q][tid];
            s1 += part[q + 1][tid];
            s2 += part[q + 2][tid];
            s3 += part[q + 3][tid];
        }
        out[b * 1024 + c * 128 + tid] = (s0 + s1) + (s2 + s3);
    }
}

// ---------------------------------------------------------------------------
extern "C" void kernel_launch(void* const* d_in, const int* in_sizes, int n_in,
                              void* d_out, int out_size)
{
    const float* si  = (const float*)d_in[0];
    const float* h   = (const float*)d_in[1];
    const float* W0  = (const float*)d_in[2];
    const float* b0  = (const float*)d_in[3];
    const float* g0  = (const float*)d_in[4];
    const float* be0 = (const float*)d_in[5];
    const float* m0  = (const float*)d_in[6];
    const float* v0  = (const float*)d_in[7];
    const float* W1  = (const float*)d_in[8];
    const float* b1  = (const float*)d_in[9];
    const float* g1  = (const float*)d_in[10];
    const float* be1 = (const float*)d_in[11];
    const float* m1  = (const float*)d_in[12];
    const float* v1  = (const float*)d_in[13];
    const float* W2  = (const float*)d_in[14];
    const float* b2  = (const float*)d_in[15];
    float* out = (float*)d_out;

    static int smem_set = 0;
    if (!smem_set) {
        cudaFuncSetAttribute(score_kernel,
                             cudaFuncAttributeMaxDynamicSharedMemorySize,
                             DYN_BYTES);
        smem_set = 1;
    }

    prep_kernel<<<B_DIM, 256>>>(si, W0, b0, g0, be0, m0, v0, b1, g1, be1, m1, v1);
    score_kernel<<<NBLK, 256, DYN_BYTES>>>(h, W0, W1, W2, b2);
    combine_kernel<<<1, 512>>>();
    wsum_kernel<<<dim3(8, B_DIM), 512>>>(h, out);
}

// round 12
// speedup vs baseline: 1.8351x; 1.2384x over previous
#include <cuda_runtime.h>
#include <cuda_bf16.h>
#include <math.h>
#include <stdint.h>

// ----------------------------------------------------------------------------
// Attention_13314398617962   (t=512, b=64, s=1024, hu=1024)
//   scores[t,b] = MLP(concat(si[b], h[t,b]))   (2048 -> 10 -> 5 -> 1, BN+relu)
//   a = softmax(scores.flatten())              (over all 32768)
//   ci[b,:] = sum_tau a[tau] * h[tau_t, tau_b, :]   (tau < 512)
// ----------------------------------------------------------------------------

#define T_DIM 512
#define B_DIM 64
#define HU 1024
#define NROWS (T_DIM * B_DIM)   // 32768
#define RPB 32                  // rows per block in score kernel
#define NBLK (NROWS / RPB)      // 1024

// dynamic smem: red[2 groups][16 it][64 partials][10] = 20480 floats (80 KB)
#define RED_FLOATS (2 * 16 * 64 * 10)
#define DYN_BYTES  (RED_FLOATS * 4)

__device__ float g_pre0[B_DIM * 10];   // si @ W0[:1024] per b (raw dot)
__device__ float g_ep[30];             // s0[10] t0[10] s1[5] t1[5]
__device__ float g_scores[T_DIM];      // raw scores for rows < 512
__device__ float g_w[T_DIM];           // softmax weights
__device__ float g_bmax[NBLK];
__device__ float g_bsum[NBLK];

// ---------------------------------------------------------------------------
__device__ __forceinline__ void ffma2(unsigned long long& d,
                                      unsigned long long a,
                                      unsigned long long b)
{
    asm("fma.rn.f32x2 %0, %1, %2, %0;" : "+l"(d) : "l"(a), "l"(b));
}
__device__ __forceinline__ void fmul2(unsigned long long& d,
                                      unsigned long long a,
                                      unsigned long long b)
{
    asm("mul.rn.f32x2 %0, %1, %2;" : "=l"(d) : "l"(a), "l"(b));
}
__device__ __forceinline__ unsigned long long pack2(float x)
{
    unsigned long long r;
    asm("mov.b64 %0, {%1, %1};" : "=l"(r) : "f"(x));
    return r;
}
__device__ __forceinline__ void unpack2(unsigned long long v, float& lo, float& hi)
{
    asm("mov.b64 {%0, %1}, %2;" : "=f"(lo), "=f"(hi) : "l"(v));
}

// ---------------------------------------------------------------------------
// K0: per-b si contribution (coalesced W0 reads) + folded BN constants.
// ---------------------------------------------------------------------------
__global__ __launch_bounds__(256)
void prep_kernel(const float* __restrict__ si,
                 const float* __restrict__ W0,
                 const float* __restrict__ b0,
                 const float* __restrict__ g0,
                 const float* __restrict__ be0,
                 const float* __restrict__ m0,
                 const float* __restrict__ v0,
                 const float* __restrict__ b1,
                 const float* __restrict__ g1,
                 const float* __restrict__ be1,
                 const float* __restrict__ m1,
                 const float* __restrict__ v1)
{
    __shared__ float red[64][10];

    int b = blockIdx.x;
    int tid = threadIdx.x;
    int lane = tid & 31;
    int warp = tid >> 5;

    float wv[40];
    {
        const float4* wp = reinterpret_cast<const float4*>(W0 + 4 * tid * 10);
#pragma unroll
        for (int i = 0; i < 10; ++i)
            reinterpret_cast<float4*>(wv)[i] = wp[i];
    }
    float4 sv = reinterpret_cast<const float4*>(si + b * 1024)[tid];

    float pj[10];
#pragma unroll
    for (int j = 0; j < 10; ++j) {
        float a = sv.x * wv[j];
        a = fmaf(sv.y, wv[10 + j], a);
        a = fmaf(sv.z, wv[20 + j], a);
        a = fmaf(sv.w, wv[30 + j], a);
        pj[j] = a;
    }
#pragma unroll
    for (int j = 0; j < 10; ++j) {
        pj[j] += __shfl_xor_sync(0xffffffffu, pj[j], 16);
        pj[j] += __shfl_xor_sync(0xffffffffu, pj[j], 8);
    }
    if (lane < 8) {
#pragma unroll
        for (int j = 0; j < 10; ++j) red[warp * 8 + lane][j] = pj[j];
    }
    __syncthreads();

    if (tid < 10) {
        float s = 0.f;
#pragma unroll
        for (int q = 0; q < 64; ++q) s += red[q][tid];
        g_pre0[b * 10 + tid] = s;
    }

    if (b == 0) {
        if (tid >= 32 && tid < 42) {
            int i = tid - 32;
            float s = g0[i] * (1.0f / sqrtf(v0[i] + 1e-5f));
            g_ep[i] = s;
            g_ep[10 + i] = (b0[i] - m0[i]) * s + be0[i];
        } else if (tid >= 64 && tid < 69) {
            int i = tid - 64;
            float s = g1[i] * (1.0f / sqrtf(v1[i] + 1e-5f));
            g_ep[20 + i] = s;
            g_ep[25 + i] = (b1[i] - m1[i]) * s + be1[i];
        }
    }
}

// ---------------------------------------------------------------------------
// K1: scores + per-block online softmax stats. 32 rows/block, 1024 blocks.
// R4 structure (proven, 48us) with 3 deltas:
//  - ONE shfl round (xor 16), lanes<16 store 5 STS.64  -> SHFL/row halved
//  - ring-3 pair prefetch (24 regs, total ~96 -> no spills at 2 CTAs/SM)
//  - red doubled to 64 partials/row-group -> 80 KB dynamic smem
// 2 row-groups x 128 threads; thread owns k = 4*ts and 512+4*ts (8 k),
// weights as 40 packed f32x2 regs.
// ---------------------------------------------------------------------------
__global__ __launch_bounds__(256, 2)
void score_kernel(const float* __restrict__ h,
                  const float* __restrict__ W0,
                  const float* __restrict__ W1,
                  const float* __restrict__ W2,
                  const float* __restrict__ b2)
{
    extern __shared__ float red[];            // [g][it][part64][10] 80 KB

    __shared__ float pre0s[RPB * 10];
    __shared__ float dsum[RPB * 10];
    __shared__ float epi[86];                 // s0 t0 s1 t1 W1[50] W2[5] b2

    int tid  = threadIdx.x;
    int g    = tid >> 7;
    int ts   = tid & 127;
    int lane = tid & 31;
    int wl   = (tid >> 5) & 3;                // warp within group
    int rowbase = blockIdx.x * RPB;
    int bbase   = rowbase & 63;

    if (tid < 30)                  epi[tid] = g_ep[tid];
    if (tid >= 32 && tid < 82)     epi[30 + tid - 32] = W1[tid - 32];
    if (tid >= 96 && tid < 101)    epi[80 + tid - 96] = W2[tid - 96];
    if (tid == 101)                epi[85] = b2[0];
    pre0s[tid] = g_pre0[bbase * 10 + tid];
    if (tid < 64) pre0s[256 + tid] = g_pre0[bbase * 10 + 256 + tid];

    // 80 weight floats as 40 packed f32x2: u[kk*5+p]
    union { float4 v[20]; unsigned long long u[40]; } wr;
    {
        const float4* wp0 = reinterpret_cast<const float4*>(W0 + (1024 + 4 * ts) * 10);
        const float4* wp1 = reinterpret_cast<const float4*>(W0 + (1536 + 4 * ts) * 10);
#pragma unroll
        for (int i = 0; i < 10; ++i) wr.v[i] = wp0[i];
#pragma unroll
        for (int i = 0; i < 10; ++i) wr.v[10 + i] = wp1[i];
    }

    const float* hb = h + (size_t)(rowbase + g) * 1024 + 4 * ts;
    float4 A[3], B[3];
#pragma unroll
    for (int i = 0; i < 3; ++i) {
        A[i] = *reinterpret_cast<const float4*>(hb + (size_t)i * 2048);
        B[i] = *reinterpret_cast<const float4*>(hb + (size_t)i * 2048 + 512);
    }

    __syncthreads();   // smem staging visible

    // slot base for this thread's partial (lane<16 stores)
    float* myred = red + g * 10240 + (wl * 16 + lane) * 10;

#pragma unroll
    for (int it = 0; it < 16; ++it) {
        int slot = it % 3;
        float4 ca = A[slot], cb = B[slot];
        if (it < 13) {
            const float* pn = hb + (size_t)(it + 3) * 2048;
            A[slot] = *reinterpret_cast<const float4*>(pn);
            B[slot] = *reinterpret_cast<const float4*>(pn + 512);
        }

        unsigned long long acc[5];
        unsigned long long hh;
        hh = pack2(ca.x);
#pragma unroll
        for (int p = 0; p < 5; ++p) fmul2(acc[p], hh, wr.u[p]);
        hh = pack2(ca.y);
#pragma unroll
        for (int p = 0; p < 5; ++p) ffma2(acc[p], hh, wr.u[5 + p]);
        hh = pack2(ca.z);
#pragma unroll
        for (int p = 0; p < 5; ++p) ffma2(acc[p], hh, wr.u[10 + p]);
        hh = pack2(ca.w);
#pragma unroll
        for (int p = 0; p < 5; ++p) ffma2(acc[p], hh, wr.u[15 + p]);
        hh = pack2(cb.x);
#pragma unroll
        for (int p = 0; p < 5; ++p) ffma2(acc[p], hh, wr.u[20 + p]);
        hh = pack2(cb.y);
#pragma unroll
        for (int p = 0; p < 5; ++p) ffma2(acc[p], hh, wr.u[25 + p]);
        hh = pack2(cb.z);
#pragma unroll
        for (int p = 0; p < 5; ++p) ffma2(acc[p], hh, wr.u[30 + p]);
        hh = pack2(cb.w);
#pragma unroll
        for (int p = 0; p < 5; ++p) ffma2(acc[p], hh, wr.u[35 + p]);

        float pj[10];
#pragma unroll
        for (int p = 0; p < 5; ++p) unpack2(acc[p], pj[2 * p], pj[2 * p + 1]);

        // ONE shfl round: lanes<16 hold sums over {lane, lane+16}
#pragma unroll
        for (int j = 0; j < 10; ++j)
            pj[j] += __shfl_xor_sync(0xffffffffu, pj[j], 16);

        if (lane < 16) {
            float2* rb = reinterpret_cast<float2*>(myred + it * 640);
#pragma unroll
            for (int p = 0; p < 5; ++p) rb[p] = make_float2(pj[2 * p], pj[2 * p + 1]);
        }
    }
    __syncthreads();

    // block reduce: 320 (row,j) sums, each over 64 partials (stride 10 floats)
#pragma unroll
    for (int pass = 0; pass < 2; ++pass) {
        int m = tid + pass * 256;
        if (m < 320) {
            int gg = m / 160;
            int rem = m - gg * 160;
            int rl = rem / 10;
            int j = rem - rl * 10;
            const float* base = red + gg * 10240 + rl * 640 + j;
            float s0 = 0.f, s1 = 0.f, s2 = 0.f, s3 = 0.f;
#pragma unroll
            for (int q = 0; q < 16; ++q) {
                s0 += base[(4 * q) * 10];
                s1 += base[(4 * q + 1) * 10];
                s2 += base[(4 * q + 2) * 10];
                s3 += base[(4 * q + 3) * 10];
            }
            dsum[(2 * rl + gg) * 10 + j] = (s0 + s1) + (s2 + s3);
        }
    }
    __syncthreads();

    // fused MLP epilogue + per-block online softmax stats (warp 0, 32 rows)
    if (tid < 32) {
        int row = rowbase + tid;
        float x0[10];
#pragma unroll
        for (int j = 0; j < 10; ++j) {
            float d = dsum[tid * 10 + j] + pre0s[tid * 10 + j];
            x0[j] = fmaxf(fmaf(d, epi[j], epi[10 + j]), 0.f);
        }
        float sc = epi[85];
#pragma unroll
        for (int i = 0; i < 5; ++i) {
            float z = 0.f;
#pragma unroll
            for (int j = 0; j < 10; ++j)
                z = fmaf(x0[j], epi[30 + j * 5 + i], z);
            float x1 = fmaxf(fmaf(z, epi[20 + i], epi[25 + i]), 0.f);
            sc = fmaf(x1, epi[80 + i], sc);
        }
        if (row < T_DIM) g_scores[row] = sc;

        float m = sc;
#pragma unroll
        for (int o = 16; o > 0; o >>= 1)
            m = fmaxf(m, __shfl_xor_sync(0xffffffffu, m, o));
        float e = expf(sc - m);
#pragma unroll
        for (int o = 16; o > 0; o >>= 1)
            e += __shfl_xor_sync(0xffffffffu, e, o);
        if (tid == 0) {
            g_bmax[blockIdx.x] = m;
            g_bsum[blockIdx.x] = e;
        }
    }
}

// ---------------------------------------------------------------------------
// K2: combine 1024 (max, expsum) pairs -> M, S; write 512 weights.
// ---------------------------------------------------------------------------
__global__ void combine_kernel()
{
    __shared__ float sm[512];
    __shared__ float MS[2];
    int tid = threadIdx.x;

    float m0v = g_bmax[tid * 2];
    float m1v = g_bmax[tid * 2 + 1];
    sm[tid] = fmaxf(m0v, m1v);
    __syncthreads();
    for (int s = 256; s > 0; s >>= 1) {
        if (tid < s) sm[tid] = fmaxf(sm[tid], sm[tid + s]);
        __syncthreads();
    }
    if (tid == 0) MS[0] = sm[0];
    __syncthreads();
    float M = MS[0];

    float ls = g_bsum[tid * 2] * expf(m0v - M)
             + g_bsum[tid * 2 + 1] * expf(m1v - M);
    sm[tid] = ls;
    __syncthreads();
    for (int s = 256; s > 0; s >>= 1) {
        if (tid < s) sm[tid] += sm[tid + s];
        __syncthreads();
    }
    if (tid == 0) MS[1] = 1.0f / sm[0];
    __syncthreads();

    g_w[tid] = expf(g_scores[tid] - M) * MS[1];
}

// ---------------------------------------------------------------------------
// K3: ci[b,:] = sum_tau w[tau] * h[tau,b,:]
// grid (8 chunks of 128 cols, 64 b) x 512 threads (16 warps, t == w mod 16).
// (R4 configuration: best measured, 24.35 us)
// ---------------------------------------------------------------------------
__global__ __launch_bounds__(512)
void wsum_kernel(const float* __restrict__ h, float* __restrict__ out)
{
    __shared__ float ws[T_DIM];
    __shared__ float part[16][128];

    int tid  = threadIdx.x;
    int w    = tid >> 5;
    int lane = tid & 31;
    int c = blockIdx.x;           // 128-col chunk
    int b = blockIdx.y;

    if (tid < 128)
        reinterpret_cast<float4*>(ws)[tid] = reinterpret_cast<const float4*>(g_w)[tid];
    __syncthreads();

    const float* hp = h + (size_t)b * 1024 + c * 128 + 4 * lane;
    float4 acc = make_float4(0.f, 0.f, 0.f, 0.f);
#pragma unroll 8
    for (int i = 0; i < T_DIM / 16; ++i) {
        int t = i * 16 + w;
        float4 hv = *reinterpret_cast<const float4*>(hp + (size_t)t * (B_DIM * HU));
        float wv = ws[t];
        acc.x = fmaf(wv, hv.x, acc.x);
        acc.y = fmaf(wv, hv.y, acc.y);
        acc.z = fmaf(wv, hv.z, acc.z);
        acc.w = fmaf(wv, hv.w, acc.w);
    }
    *reinterpret_cast<float4*>(&part[w][4 * lane]) = acc;
    __syncthreads();

    if (tid < 128) {
        float s0 = part[0][tid], s1 = part[1][tid];
        float s2 = part[2][tid], s3 = part[3][tid];
#pragma unroll
        for (int q = 4; q < 16; q += 4) {
            s0 += part[q][tid];
            s1 += part[q + 1][tid];
            s2 += part[q + 2][tid];
            s3 += part[q + 3][tid];
        }
        out[b * 1024 + c * 128 + tid] = (s0 + s1) + (s2 + s3);
    }
}

// ---------------------------------------------------------------------------
extern "C" void kernel_launch(void* const* d_in, const int* in_sizes, int n_in,
                              void* d_out, int out_size)
{
    const float* si  = (const float*)d_in[0];
    const float* h   = (const float*)d_in[1];
    const float* W0  = (const float*)d_in[2];
    const float* b0  = (const float*)d_in[3];
    const float* g0  = (const float*)d_in[4];
    const float* be0 = (const float*)d_in[5];
    const float* m0  = (const float*)d_in[6];
    const float* v0  = (const float*)d_in[7];
    const float* W1  = (const float*)d_in[8];
    const float* b1  = (const float*)d_in[9];
    const float* g1  = (const float*)d_in[10];
    const float* be1 = (const float*)d_in[11];
    const float* m1  = (const float*)d_in[12];
    const float* v1  = (const float*)d_in[13];
    const float* W2  = (const float*)d_in[14];
    const float* b2  = (const float*)d_in[15];
    float* out = (float*)d_out;

    static int smem_set = 0;
    if (!smem_set) {
        cudaFuncSetAttribute(score_kernel,
                             cudaFuncAttributeMaxDynamicSharedMemorySize,
                             DYN_BYTES);
        smem_set = 1;
    }

    prep_kernel<<<B_DIM, 256>>>(si, W0, b0, g0, be0, m0, v0, b1, g1, be1, m1, v1);
    score_kernel<<<NBLK, 256, DYN_BYTES>>>(h, W0, W1, W2, b2);
    combine_kernel<<<1, 512>>>();
    wsum_kernel<<<dim3(8, B_DIM), 512>>>(h, out);
}